// round 17
// baseline (speedup 1.0000x reference)
#include <cuda_runtime.h>
#include <cuda_bf16.h>

#define HH 1024
#define WW 1024
#define NB 8
#define PLANE (HH * WW)

typedef unsigned long long u64;

// ---- packed fp32x2 helpers (sm_103a FFMA2 path, PTX-only) ----
__device__ __forceinline__ u64 pk(float lo, float hi) {
    u64 r; asm("mov.b64 %0, {%1, %2};" : "=l"(r) : "f"(lo), "f"(hi)); return r;
}
__device__ __forceinline__ void upk(u64 v, float& lo, float& hi) {
    asm("mov.b64 {%0, %1}, %2;" : "=f"(lo), "=f"(hi) : "l"(v));
}
__device__ __forceinline__ u64 fma2(u64 a, u64 b, u64 c) {
    u64 d; asm("fma.rn.f32x2 %0, %1, %2, %3;" : "=l"(d) : "l"(a), "l"(b), "l"(c));
    return d;
}

// Load the 4-wide window (cols -1..+2 around p) of one row. One aligned
// LDG.64 + two predicated edge scalars; all three independent (preserve MLP —
// no shuffles / smem staging / prefetch / packed x, per R2/R5/R8/R14).
__device__ __forceinline__ void load_win4(const float* __restrict__ p,
                                          bool lft, bool rgt, float v[4]) {
    float2 m = *reinterpret_cast<const float2*>(p);
    v[1] = m.x; v[2] = m.y;
    v[0] = lft ? p[-1] : 0.0f;
    v[3] = rgt ? p[2]  : 0.0f;
}

__global__ void __launch_bounds__(128, 7)
small_sm_block_kernel(const float* __restrict__ image,
                      const float* __restrict__ x,
                      const float* __restrict__ wgt,   // (9,1,3,3) = 81
                      const float* __restrict__ bias,  // (9,)
                      float* __restrict__ y) {
    __shared__ u64 sw2[81];   // weight duplicated into both halves
    __shared__ u64 sb2[9];
    const int t = threadIdx.x;
    if (t < 81) { float w = wgt[t];  sw2[t] = pk(w, w); }
    if (t < 9)  { float b = bias[t]; sb2[t] = pk(b, b); }
    __syncthreads();

    const int h0 = blockIdx.y * 2;                  // output rows h0, h0+1
    const int w0 = (blockIdx.x * 128 + t) * 2;      // output cols w0, w0+1

    // Hoisted bounds (block-uniform rows; thread-constant cols).
    const bool top = h0 > 0;
    const bool bot = h0 + 2 < HH;
    const bool lft = w0 > 0;
    const bool rgt = w0 + 2 < WW;

    // ---- image window: 4 rows (h0-1..h0+2) x 4 cols ----
    const float* ip = image + (h0 - 1) * WW + w0;
    float img[4][4];
    if (top) load_win4(ip, lft, rgt, img[0]);
    else     { img[0][0] = img[0][1] = img[0][2] = img[0][3] = 0.f; }
    load_win4(ip + WW,     lft, rgt, img[1]);
    load_win4(ip + 2 * WW, lft, rgt, img[2]);
    if (bot) load_win4(ip + 3 * WW, lft, rgt, img[3]);
    else     { img[3][0] = img[3][1] = img[3][2] = img[3][3] = 0.f; }

    // ---- K-build, packed over the two output columns (FFMA2):
    //      pr[r][d] = (img[r][d], img[r][d+1]); img scalars die here. ----
    u64 pr[4][3];
#pragma unroll
    for (int r = 0; r < 4; r++)
#pragma unroll
        for (int d = 0; d < 3; d++) pr[r][d] = pk(img[r][d], img[r][d + 1]);

    u64 KAp[9], KBp[9];
#pragma unroll
    for (int j = 0; j < 9; j++) {
        u64 b2 = sb2[j];
        KAp[j] = b2; KBp[j] = b2;
#pragma unroll
        for (int a = 0; a < 3; a++)
#pragma unroll
            for (int d = 0; d < 3; d++) {
                u64 w2 = sw2[j * 9 + a * 3 + d];
                KAp[j] = fma2(pr[a][d],     w2, KAp[j]);
                KBp[j] = fma2(pr[a + 1][d], w2, KBp[j]);
            }
    }

    // ---- unpack once to scalar K for the (unchanged, scalar) apply ----
    float KA[9][2], KB[9][2];
#pragma unroll
    for (int j = 0; j < 9; j++) {
        upk(KAp[j], KA[j][0], KA[j][1]);
        upk(KBp[j], KB[j][0], KB[j][1]);
    }

    // ---- apply: full unroll + pointer-bump addressing (champion R16) ----
    const float* xp = x + (h0 - 1) * WW + w0;
    float*       yp = y + h0 * WW + w0;
#pragma unroll
    for (int b = 0; b < NB; b++) {
        float xr[4][4];
        if (top) load_win4(xp, lft, rgt, xr[0]);
        else     { xr[0][0] = xr[0][1] = xr[0][2] = xr[0][3] = 0.f; }
        load_win4(xp + WW,     lft, rgt, xr[1]);
        load_win4(xp + 2 * WW, lft, rgt, xr[2]);
        if (bot) load_win4(xp + 3 * WW, lft, rgt, xr[3]);
        else     { xr[3][0] = xr[3][1] = xr[3][2] = xr[3][3] = 0.f; }

        float a0 = 0.f, a1 = 0.f, b0 = 0.f, b1 = 0.f;
#pragma unroll
        for (int a = 0; a < 3; a++) {
#pragma unroll
            for (int d = 0; d < 3; d++) {
                const int j = a * 3 + d;
                a0 += xr[a][d]         * KA[j][0];
                a1 += xr[a][d + 1]     * KA[j][1];
                b0 += xr[a + 1][d]     * KB[j][0];
                b1 += xr[a + 1][d + 1] * KB[j][1];
            }
        }

        float2 oA; oA.x = a0; oA.y = a1;
        float2 oB; oB.x = b0; oB.y = b1;
        *reinterpret_cast<float2*>(yp)      = oA;   // row h0
        *reinterpret_cast<float2*>(yp + WW) = oB;   // row h0+1

        xp += PLANE;
        yp += PLANE;
    }
}

extern "C" void kernel_launch(void* const* d_in, const int* in_sizes, int n_in,
                              void* d_out, int out_size) {
    const float* image = (const float*)d_in[0];  // (1, 1024, 1024)
    const float* x     = (const float*)d_in[1];  // (8, 1, 1024, 1024)
    const float* klw   = (const float*)d_in[2];  // (9, 1, 3, 3)
    const float* klb   = (const float*)d_in[3];  // (9,)
    float* y = (float*)d_out;                    // (8, 1, 1024, 1024)

    dim3 block(128);
    dim3 grid(WW / 2 / 128, HH / 2);  // (4, 512) = 2048 blocks
    small_sm_block_kernel<<<grid, block>>>(image, x, klw, klb, y);
}